// round 16
// baseline (speedup 1.0000x reference)
#include <cuda_runtime.h>
#include <cuda_bf16.h>

#define BOLTZMAN 0.001987191f
#define L 64

// Coefficients, written by gle_coef_kernel, read by main kernel (after PDL
// sync when PDL is active; plain stream order otherwise).
__device__ __align__(16) float g_cA[L];  // g_cA[s] = -mk[64-s] (s>=1), [0]=0
__device__ __align__(16) float g_cB[L];  // g_cB[s] =  h[64-s]  (s>=1), [0]=0
__device__ float g_sc[2];                // [0] = -mk[0], [1] = h[0]

// Tiny coefficient kernel: 1 block, 64 threads.
__global__ void gle_coef_kernel(const float* __restrict__ h,
                                const int* __restrict__ Traw,
                                const float* __restrict__ mass) {
    __shared__ float hs[L];
    int k = threadIdx.x;
    hs[k] = h[k];
    __syncthreads();

    float mk = 0.0f;
    #pragma unroll 8
    for (int j = 0; j + k < L; ++j) mk += hs[j] * hs[j + k];

    int ti = Traw[0];
    float T = (ti > 0 && ti < 10000000) ? (float)ti : __int_as_float(ti);
    mk *= mass[0] * BOLTZMAN * T;

    if (k == 0) {
        g_sc[0] = -mk;
        g_sc[1] = hs[0];
        g_cA[0] = 0.0f;
        g_cB[0] = 0.0f;
    } else {
        g_cA[L - k] = -mk;
        g_cB[L - k] = hs[k];
    }
}

// One-shot streaming kernel, 64-thread blocks (8 channels/block):
// up to 32 independent CTAs per SM (HW limit) with staggered starts ->
// maximal epilogue phase decorrelation; each block's no-loads-in-flight
// tail covers only 2 warps. Body identical to the best (R15) kernel:
// 2 adjacent channels/thread, evict-first loads, broadcast scalars,
// single float2 store.
__global__ void __launch_bounds__(64) gle_main_kernel(
    const float* __restrict__ v,
    const float* __restrict__ vlist,
    const float* __restrict__ wlist,
    const float* __restrict__ wnew,
    float* __restrict__ out,
    int nch) {
    int tid = threadIdx.x;
    int grp = tid >> 4;                 // 0..3
    int q   = tid & 15;                 // float4 index within 64-float row

    int c0 = blockIdx.x * 8 + grp * 2;  // even channel
    int c1 = c0 + 1;                    // odd channel (adjacent)
    bool ok0 = (c0 < nch), ok1 = (c1 < nch);
    int p0 = ok0 ? c0 : 0, p1 = ok1 ? c1 : 0;

    const float4* vl4 = (const float4*)vlist;
    const float4* wl4 = (const float4*)wlist;

    // ---- front-batched streaming loads (evict-first, touched once) ----
    const float4 a0 = __ldcs(vl4 + p0 * 16 + q);
    const float4 b0 = __ldcs(wl4 + p0 * 16 + q);
    const float4 a1 = __ldcs(vl4 + p1 * 16 + q);
    const float4 b1 = __ldcs(wl4 + p1 * 16 + q);

    // ---- scalar terms: broadcast loads, no divergence ----
    const float vv0 = __ldg(&v[p0]);
    const float wn0 = __ldg(&wnew[p0]);
    const float vv1 = __ldg(&v[p1]);
    const float wn1 = __ldg(&wnew[p1]);

    // ---- PDL sync: coef kernel hidden under the load ramp above.
    //      No-op if launched without the PDL attribute. ----
    cudaGridDependencySynchronize();

    const float4 ca = __ldg(&((const float4*)g_cA)[q]);
    const float4 cb = __ldg(&((const float4*)g_cB)[q]);
    const float s0 = __ldg(&g_sc[0]);
    const float s1 = __ldg(&g_sc[1]);

    float acc0 = a0.x * ca.x + a0.y * ca.y + a0.z * ca.z + a0.w * ca.w
               + b0.x * cb.x + b0.y * cb.y + b0.z * cb.z + b0.w * cb.w;
    float acc1 = a1.x * ca.x + a1.y * ca.y + a1.z * ca.z + a1.w * ca.w
               + b1.x * cb.x + b1.y * cb.y + b1.z * cb.z + b1.w * cb.w;

    // width-16 reduction, two chains interleaved
    acc0 += __shfl_down_sync(0xffffffffu, acc0, 8, 16);
    acc1 += __shfl_down_sync(0xffffffffu, acc1, 8, 16);
    acc0 += __shfl_down_sync(0xffffffffu, acc0, 4, 16);
    acc1 += __shfl_down_sync(0xffffffffu, acc1, 4, 16);
    acc0 += __shfl_down_sync(0xffffffffu, acc0, 2, 16);
    acc1 += __shfl_down_sync(0xffffffffu, acc1, 2, 16);
    acc0 += __shfl_down_sync(0xffffffffu, acc0, 1, 16);
    acc1 += __shfl_down_sync(0xffffffffu, acc1, 1, 16);

    if (q == 0) {
        float r0 = acc0 + vv0 * s0 + wn0 * s1;
        float r1 = acc1 + vv1 * s0 + wn1 * s1;
        if (ok1) {
            float2 r = make_float2(r0, r1);
            *reinterpret_cast<float2*>(out + c0) = r;
        } else if (ok0) {
            out[c0] = r0;
        }
    }
}

extern "C" void kernel_launch(void* const* d_in, const int* in_sizes, int n_in,
                              void* d_out, int out_size) {
    // metadata order: v, T, dt, mass, h, v_list, w_list, w_new
    const float* v     = (const float*)d_in[0];
    const int*   Traw  = (const int*)  d_in[1];
    const float* mass  = (const float*)d_in[3];
    const float* h     = (const float*)d_in[4];
    const float* vlist = (const float*)d_in[5];
    const float* wlist = (const float*)d_in[6];
    const float* wnew  = (const float*)d_in[7];
    float* out = (float*)d_out;

    int nch = in_sizes[0];                 // 3*NATOM channels

    gle_coef_kernel<<<1, 64>>>(h, Traw, mass);

    int blocks = (nch + 7) / 8;

    // Preferred path: PDL launch so the main kernel's load ramp hides the
    // coef kernel + launch gap.
    cudaLaunchAttribute attrs[1];
    attrs[0].id = cudaLaunchAttributeProgrammaticStreamSerialization;
    attrs[0].val.programmaticStreamSerializationAllowed = 1;

    cudaLaunchConfig_t cfg = {};
    cfg.gridDim = dim3((unsigned)blocks, 1, 1);
    cfg.blockDim = dim3(64, 1, 1);
    cfg.dynamicSmemBytes = 0;
    cfg.stream = 0;
    cfg.attrs = attrs;
    cfg.numAttrs = 1;

    cudaError_t e = cudaLaunchKernelEx(&cfg, gle_main_kernel,
                                       v, vlist, wlist, wnew, out, nch);
    if (e != cudaSuccess) {
        (void)cudaGetLastError();
        gle_main_kernel<<<blocks, 64>>>(v, vlist, wlist, wnew, out, nch);
    }
}